// round 15
// baseline (speedup 1.0000x reference)
#include <cuda_runtime.h>
#include <cuda_bf16.h>

// IDW interpolation, POWER=2:  w = 1/d^2 (sqrt cancels).
//
// Round 14: SCALAR + PAIRING (never tested together; all pairing rounds
// were f32x2-packed). Five rounds pinned the packed formulation at ~46us:
// wide f32x2 ops dual-pump (2 issue slots each) so packing buys no issue
// advantage, and it ADDS a large alu-pipe MOV tax (pack/unpack around
// every rcp + register-pair marshaling; alu pipe 33-55% across rounds).
// Scalar pairing: identical 14 FP slots per (2 stations x 1 point), but
// rcp.approx consumes a scalar directly (zero MOVs), station pair loads
// naturally as one float4 (x1,y1,x2,y2) + float2 (v1,v2) (2 LDS vs 3),
// no 64-bit register pairs, ~40 regs.
//
// Pairing identity for d2 values a,b (1 MUFU.RCP per 2 stations/point):
//   w1+w2       = (a+b)/(a*b)
//   w1*v1+w2*v2 = (v1*b + v2*a)/(a*b)
// d==0: fold +1e-12 into d^2 (dominating weight -> same interpolated
// value; no branch; pair product can't underflow).
//
// Shape: 8 split-warps per block (64 stations each), 4 points per thread,
// 128 points per block, 2048 blocks, 16384 warps, fused smem reduction.

#define NSTATIONS 512
#define SPLITS 8
#define PAIRS_PER_SPLIT 32             // 64 stations per split-warp
#define CHAINS 4                       // points per thread
#define POINTS_PER_BLOCK 128           // 32 lanes * 4 chains
#define TPB 256                        // 8 warps: split = warp id

__device__ __forceinline__ float frcp(float a) {
    float r; asm("rcp.approx.f32 %0, %1;" : "=f"(r) : "f"(a)); return r;
}

__global__ __launch_bounds__(TPB) void idw_scalar(
    const float* __restrict__ station_coords,  // (B, S, 2)
    const float* __restrict__ station_values,  // (B, S)
    const float* __restrict__ grid_points,     // (B, P, 2)
    float* __restrict__ out,                   // (B, P) flat
    int P)
{
    // 256 station pairs: coords as float4 (x1,y1,x2,y2), values as float2.
    __shared__ float4 sh_c[NSTATIONS / 2];            // 4 KB
    __shared__ float2 sh_v[NSTATIONS / 2];            // 2 KB
    __shared__ float2 red[SPLITS * POINTS_PER_BLOCK]; // 8 KB partials (w, wv)

    const int tid   = threadIdx.x;
    const int split = tid >> 5;                    // warp id, 0..7
    const int lane  = tid & 31;
    const int pointbase = blockIdx.x * POINTS_PER_BLOCK;
    const int b = pointbase / P;  // 128 | P: block stays in one batch

    // Stage one station pair per thread: 1 LDG.128 + 1 LDG.64 -> direct copy.
    {
        sh_c[tid] = reinterpret_cast<const float4*>(
            station_coords + (size_t)b * NSTATIONS * 2)[tid];
        sh_v[tid] = reinterpret_cast<const float2*>(
            station_values + (size_t)b * NSTATIONS)[tid];
    }
    __syncthreads();

    // 4 points per thread: chain q owns local point (32q + lane). Coalesced.
    float gx[CHAINS], gy[CHAINS], ws[CHAINS], vs[CHAINS];
    #pragma unroll
    for (int q = 0; q < CHAINS; q++) {
        const float2 g = reinterpret_cast<const float2*>(
            grid_points)[(size_t)pointbase + 32 * q + lane];
        gx[q] = g.x;
        gy[q] = g.y;
        ws[q] = 0.0f;
        vs[q] = 0.0f;
    }

    const float4* cb = sh_c + split * PAIRS_PER_SPLIT;
    const float2* vb = sh_v + split * PAIRS_PER_SPLIT;

    #pragma unroll 4
    for (int p = 0; p < PAIRS_PER_SPLIT; p++) {
        const float4 c = cb[p];   // (x1, y1, x2, y2)  LDS.128 broadcast
        const float2 v = vb[p];   // (v1, v2)          LDS.64 broadcast

        #pragma unroll
        for (int q = 0; q < CHAINS; q++) {   // 4 independent scalar chains
            float dx1 = gx[q] - c.x;
            float dy1 = gy[q] - c.y;
            float a   = fmaf(dy1, dy1, 1e-12f);
            a         = fmaf(dx1, dx1, a);       // d2 of station 1
            float dx2 = gx[q] - c.z;
            float dy2 = gy[q] - c.w;
            float bb  = fmaf(dy2, dy2, 1e-12f);
            bb        = fmaf(dx2, dx2, bb);      // d2 of station 2
            float sum  = a + bb;                 // a + b
            float prod = a * bb;                 // a * b
            float num  = fmaf(v.y, a, v.x * bb); // v1*b + v2*a
            float r    = frcp(prod);             // ONE scalar MUFU.RCP, no MOVs
            ws[q] = fmaf(sum, r, ws[q]);
            vs[q] = fmaf(num, r, vs[q]);
        }
    }

    // Partials -> smem
    #pragma unroll
    for (int q = 0; q < CHAINS; q++)
        red[split * POINTS_PER_BLOCK + 32 * q + lane] = make_float2(ws[q], vs[q]);
    __syncthreads();

    // Threads 0..127 reduce 8 splits for one point each (fixed order, det.)
    if (tid < POINTS_PER_BLOCK) {
        float2 acc = red[tid];
        #pragma unroll
        for (int k = 1; k < SPLITS; k++) {
            float2 t = red[k * POINTS_PER_BLOCK + tid];  // LDS.64, conflict-free
            acc.x += t.x;
            acc.y += t.y;
        }
        out[(size_t)pointbase + tid] = acc.y * frcp(acc.x);  // coalesced STG.32
    }
}

extern "C" void kernel_launch(void* const* d_in, const int* in_sizes, int n_in,
                              void* d_out, int out_size) {
    const float* station_coords = (const float*)d_in[0];  // (B,S,2)
    const float* station_values = (const float*)d_in[1];  // (B,S)
    const float* grid_points    = (const float*)d_in[2];  // (B,P,2)
    float* out = (float*)d_out;

    const int S = NSTATIONS;                 // 512 per problem spec
    const int B = in_sizes[1] / S;           // 2
    const int P = in_sizes[2] / (B * 2);     // 131072

    const int total_points = B * P;                        // 262144
    const int blocks = total_points / POINTS_PER_BLOCK;    // 2048, 16384 warps
    idw_scalar<<<blocks, TPB>>>(station_coords, station_values, grid_points,
                                out, P);
}

// round 16
// speedup vs baseline: 1.1428x; 1.1428x over previous
#include <cuda_runtime.h>
#include <cuda_bf16.h>

// IDW interpolation, POWER=2:  w = 1/d^2 (sqrt cancels).
//
// Round 15: packed (R9 shape, best measured) with the MUFU rcp replaced by
// a FULLY-PACKED Newton reciprocal -- removes every scalar<->pair register
// crossing (the measured 1.46x MOV bloat) and all MUFU dependency tails.
//
// Negative magic seed: nr0_bits = 0xFEF311C3FEF311C3 - bits(prod) computes
// an approximation of -1/prod for BOTH f32x2 lanes in ONE u64 subtract
// (sign-bit-set magic; cross-lane borrow impossible since any positive
// float's bits < 0xFEF311C3). Two Newton steps in pure f32x2:
//     t = fma(prod, nr, 2);  nr = nr * t        (nr stays negative)
// rel err: 0.049 -> 2.4e-3 -> ~6e-6.
// The negation is free: accumulate NEGATED sums (nws += sum*nr,
// nvs += num*nr) and the final division nvs/nws cancels the signs.
//
// Pairing identity for d2 values a,b (1 reciprocal per 2 stations/point):
//   w1+w2       = (a+b)/(a*b)
//   w1*v1+w2*v2 = (v1*b + v2*a)/(a*b)
// d==0: fold +1e-12 into d^2 (dominating weight -> same ratio; no branch;
// pair product can't underflow; prod in [~1e-21, 16] -> seed valid).

#define NSTATIONS 512
#define SPLITS 8
#define PAIRS_PER_SPLIT 32             // 64 stations per split-warp
#define CHAINS 4                       // point-packs per thread (8 points)
#define PACKS_PER_BLOCK 128            // 32 lanes * 4 chains
#define TPB 256                        // 8 warps: split = warp id
#define NPACKS 131072                  // total points / 2

typedef unsigned long long u64;

#define NMAGIC 0xFEF311C3FEF311C3ULL   // negative-reciprocal seed, both lanes

__device__ __forceinline__ u64 f2_pack(float lo, float hi) {
    u64 r; asm("mov.b64 %0, {%1, %2};" : "=l"(r) : "f"(lo), "f"(hi)); return r;
}
__device__ __forceinline__ void f2_unpack(u64 a, float& lo, float& hi) {
    asm("mov.b64 {%0, %1}, %2;" : "=f"(lo), "=f"(hi) : "l"(a));
}
__device__ __forceinline__ u64 f2_add(u64 a, u64 b) {
    u64 r; asm("add.rn.f32x2 %0, %1, %2;" : "=l"(r) : "l"(a), "l"(b)); return r;
}
__device__ __forceinline__ u64 f2_mul(u64 a, u64 b) {
    u64 r; asm("mul.rn.f32x2 %0, %1, %2;" : "=l"(r) : "l"(a), "l"(b)); return r;
}
__device__ __forceinline__ u64 f2_fma(u64 a, u64 b, u64 c) {
    u64 r; asm("fma.rn.f32x2 %0, %1, %2, %3;" : "=l"(r) : "l"(a), "l"(b), "l"(c)); return r;
}
__device__ __forceinline__ float frcp(float a) {
    float r; asm("rcp.approx.f32 %0, %1;" : "=f"(r) : "f"(a)); return r;
}
// Packed negative reciprocal: nr ~ -1/a, entirely in pair-register domain.
__device__ __forceinline__ u64 f2_nrcp(u64 a, u64 two) {
    u64 nr = NMAGIC - a;                  // one u64 sub: seed both lanes
    u64 t  = f2_fma(a, nr, two);          // t = 2 - a*|r|
    nr     = f2_mul(nr, t);               // Newton 1
    t      = f2_fma(a, nr, two);
    nr     = f2_mul(nr, t);               // Newton 2: rel err ~6e-6
    return nr;
}

__global__ __launch_bounds__(TPB) void idw_fused(
    const float* __restrict__ station_coords,  // (B, S, 2)
    const float* __restrict__ station_values,  // (B, S)
    const float* __restrict__ grid_points,     // (B, P, 2)
    float* __restrict__ out,                   // (B, P) flat
    int P)
{
    // 256 station pairs, 6 u64 each (3 x 16B -> LDS.128 broadcast):
    //  [0]=(-x1,-x1) [1]=(-y1,-y1) [2]=(-x2,-x2) [3]=(-y2,-y2) [4]=(v1,v1) [5]=(v2,v2)
    __shared__ u64 sh[(NSTATIONS / 2) * 6];           // 12 KB
    __shared__ float4 red[SPLITS * PACKS_PER_BLOCK];  // 16 KB partials

    const int tid   = threadIdx.x;
    const int split = tid >> 5;                    // warp id, 0..7
    const int lane  = tid & 31;
    const int packbase = blockIdx.x * PACKS_PER_BLOCK;
    const int b = (packbase * 2) / P;  // 256 points/block divides P: one batch

    // Stage: one station pair per thread (LDG.128 + LDG.64 -> 3x STS.128)
    {
        const float4 c = reinterpret_cast<const float4*>(
            station_coords + (size_t)b * NSTATIONS * 2)[tid];
        const float2 v = reinterpret_cast<const float2*>(
            station_values + (size_t)b * NSTATIONS)[tid];
        ulonglong2* dst = reinterpret_cast<ulonglong2*>(sh + tid * 6);
        dst[0] = make_ulonglong2(f2_pack(-c.x, -c.x), f2_pack(-c.y, -c.y));
        dst[1] = make_ulonglong2(f2_pack(-c.z, -c.z), f2_pack(-c.w, -c.w));
        dst[2] = make_ulonglong2(f2_pack(v.x, v.x),   f2_pack(v.y, v.y));
    }
    __syncthreads();

    // 4 packs per thread: chain q owns pack (lane + 32*q). Coalesced float4.
    u64 gx[CHAINS], gy[CHAINS], nws[CHAINS], nvs[CHAINS];
    #pragma unroll
    for (int q = 0; q < CHAINS; q++) {
        const float4 a = reinterpret_cast<const float4*>(
            grid_points)[packbase + 32 * q + lane];
        gx[q] = f2_pack(a.x, a.z);
        gy[q] = f2_pack(a.y, a.w);
        nws[q] = 0ull;   // accumulates -sum(w)
        nvs[q] = 0ull;   // accumulates -sum(w*v)
    }

    const u64 eps2 = f2_pack(1e-12f, 1e-12f);
    const u64 two2 = f2_pack(2.0f, 2.0f);
    const ulonglong2* sh2 = reinterpret_cast<const ulonglong2*>(sh)
                          + (size_t)split * PAIRS_PER_SPLIT * 3;

    #pragma unroll 2
    for (int p = 0; p < PAIRS_PER_SPLIT; p++) {
        const ulonglong2 c1 = sh2[p * 3 + 0];  // (nx1, ny1)  LDS.128 broadcast
        const ulonglong2 c2 = sh2[p * 3 + 1];  // (nx2, ny2)
        const ulonglong2 vv = sh2[p * 3 + 2];  // (vv1, vv2)

        #pragma unroll
        for (int q = 0; q < CHAINS; q++) {     // 4 independent chains
            u64 dx1 = f2_add(gx[q], c1.x);
            u64 dy1 = f2_add(gy[q], c1.y);
            u64 da  = f2_fma(dy1, dy1, eps2);
            da      = f2_fma(dx1, dx1, da);        // a = d2 of station 1
            u64 dx2 = f2_add(gx[q], c2.x);
            u64 dy2 = f2_add(gy[q], c2.y);
            u64 db  = f2_fma(dy2, dy2, eps2);
            db      = f2_fma(dx2, dx2, db);        // b = d2 of station 2
            u64 sum  = f2_add(da, db);             // a + b
            u64 prod = f2_mul(da, db);             // a * b
            u64 num  = f2_mul(vv.x, db);
            num      = f2_fma(vv.y, da, num);      // v1*b + v2*a
            u64 nr   = f2_nrcp(prod, two2);        // -1/(a*b), pure f32x2
            nws[q] = f2_fma(sum, nr, nws[q]);      // -= (w1+w2)
            nvs[q] = f2_fma(num, nr, nvs[q]);      // -= (w1 v1 + w2 v2)
        }
    }

    // Partials -> smem (negated sums; signs cancel at final division)
    #pragma unroll
    for (int q = 0; q < CHAINS; q++) {
        float w0, w1, n0, n1;
        f2_unpack(nws[q], w0, w1);
        f2_unpack(nvs[q], n0, n1);
        red[split * PACKS_PER_BLOCK + 32 * q + lane] = make_float4(w0, w1, n0, n1);
    }
    __syncthreads();

    // Threads 0..127 reduce 8 splits for one pack each (fixed order, det.)
    if (tid < PACKS_PER_BLOCK) {
        float4 acc = red[tid];
        #pragma unroll
        for (int k = 1; k < SPLITS; k++) {
            float4 t = red[k * PACKS_PER_BLOCK + tid];  // conflict-free LDS.128
            acc.x += t.x; acc.y += t.y; acc.z += t.z; acc.w += t.w;
        }
        float2 r;
        r.x = acc.z * frcp(acc.x);   // (-sum wv)/(-sum w) = interpolated
        r.y = acc.w * frcp(acc.y);
        reinterpret_cast<float2*>(out)[packbase + tid] = r;
    }
}

extern "C" void kernel_launch(void* const* d_in, const int* in_sizes, int n_in,
                              void* d_out, int out_size) {
    const float* station_coords = (const float*)d_in[0];  // (B,S,2)
    const float* station_values = (const float*)d_in[1];  // (B,S)
    const float* grid_points    = (const float*)d_in[2];  // (B,P,2)
    float* out = (float*)d_out;

    const int S = NSTATIONS;                 // 512 per problem spec
    const int B = in_sizes[1] / S;           // 2
    const int P = in_sizes[2] / (B * 2);     // 131072

    const int blocks = NPACKS / PACKS_PER_BLOCK;  // 1024 blocks, 8192 warps
    idw_fused<<<blocks, TPB>>>(station_coords, station_values, grid_points,
                               out, P);
}